// round 1
// baseline (speedup 1.0000x reference)
#include <cuda_runtime.h>
#include <math.h>

#define NROW 8192
#define DIN  512
#define DH   256
#define SLOPE 0.1f
#define CHUNK 64
#define NCHUNK (NROW / CHUNK)   // 128

// ---------------- scratch (device globals: no allocation allowed) ----------------
__device__ float  g_h[NROW * DH];                 // 8 MB
__device__ float  g_s1[NROW];
__device__ float  g_s2[NROW];
__device__ float  g_s2max;
__device__ int    g_rank[NROW];
__device__ float  g_pj[NROW], g_qj[NROW];         // original order
__device__ float  g_s2s[NROW];                    // sorted s2
__device__ int    g_perm[NROW];                   // sorted -> original
__device__ float  g_ps[NROW], g_qs[NROW];         // sorted order
__device__ double g_PreP[(NROW + 1) * DH];        // exclusive prefix of p*h (sorted)
__device__ double g_PreQ[(NROW + 1) * DH];        // exclusive prefix of q*h (sorted)
__device__ double g_SpPre[NROW + 1];
__device__ double g_SqPre[NROW + 1];
__device__ double g_chP[NCHUNK * DH], g_chQ[NCHUNK * DH];
__device__ double g_chSp[NCHUNK], g_chSq[NCHUNK];
__device__ float  g_rowA[NROW], g_rowB[NROW], g_rowT[NROW];   // alpha/Z, beta/Z, threshold

// ---------------- K1: h = doc @ W + W_b  (fp32 SGEMM 128x128x16) ----------------
__global__ __launch_bounds__(256, 2) void k_gemm(const float* __restrict__ doc,
                                                 const float* __restrict__ W,
                                                 const float* __restrict__ Wb) {
    __shared__ float As[16][128];
    __shared__ float Bs[16][128];
    const int bm = blockIdx.x * 128;
    const int bn = blockIdx.y * 128;
    const int tid = threadIdx.x;
    const int tr = tid / 16, tc = tid % 16;
    float acc[8][8];
#pragma unroll
    for (int i = 0; i < 8; i++)
#pragma unroll
        for (int j = 0; j < 8; j++) acc[i][j] = 0.f;

    for (int k0 = 0; k0 < DIN; k0 += 16) {
#pragma unroll
        for (int l = 0; l < 2; l++) {
            int f = tid + l * 256;                  // [0, 512)
            int ar = f >> 2, ac4 = (f & 3) << 2;    // A: 128 rows x 16 k
            float4 v = *(const float4*)&doc[(size_t)(bm + ar) * DIN + k0 + ac4];
            As[ac4 + 0][ar] = v.x; As[ac4 + 1][ar] = v.y;
            As[ac4 + 2][ar] = v.z; As[ac4 + 3][ar] = v.w;
            int br = f >> 5, bc4 = (f & 31) << 2;   // B: 16 k x 128 n
            float4 w = *(const float4*)&W[(size_t)(k0 + br) * DH + bn + bc4];
            *(float4*)&Bs[br][bc4] = w;
        }
        __syncthreads();
#pragma unroll
        for (int kk = 0; kk < 16; kk++) {
            float a[8], b[8];
#pragma unroll
            for (int i = 0; i < 4; i++) {
                ((float4*)a)[0] = *(float4*)&As[kk][tr * 8];
                ((float4*)a)[1] = *(float4*)&As[kk][tr * 8 + 4];
                ((float4*)b)[0] = *(float4*)&Bs[kk][tc * 8];
                ((float4*)b)[1] = *(float4*)&Bs[kk][tc * 8 + 4];
                break;
            }
#pragma unroll
            for (int i = 0; i < 8; i++)
#pragma unroll
                for (int j = 0; j < 8; j++) acc[i][j] += a[i] * b[j];
        }
        __syncthreads();
    }
#pragma unroll
    for (int i = 0; i < 8; i++) {
        int r = bm + tr * 8 + i;
#pragma unroll
        for (int j = 0; j < 8; j += 4) {
            int c = bn + tc * 8 + j;
            float4 o;
            o.x = acc[i][j + 0] + Wb[c + 0];
            o.y = acc[i][j + 1] + Wb[c + 1];
            o.z = acc[i][j + 2] + Wb[c + 2];
            o.w = acc[i][j + 3] + Wb[c + 3];
            *(float4*)&g_h[(size_t)r * DH + c] = o;
        }
    }
}

// ---------------- K2: s1 = h@a1, s2 = h@a2 (warp per row) ----------------
__global__ void k_s(const float* __restrict__ a) {
    int warp = (blockIdx.x * blockDim.x + threadIdx.x) >> 5;
    int lane = threadIdx.x & 31;
    if (warp >= NROW) return;
    const float* hr = &g_h[(size_t)warp * DH];
    float s1 = 0.f, s2 = 0.f;
#pragma unroll
    for (int u = 0; u < 8; u++) {
        int c = u * 32 + lane;
        float hv = hr[c];
        s1 += hv * __ldg(&a[c]);
        s2 += hv * __ldg(&a[c + DH]);
    }
#pragma unroll
    for (int o = 16; o > 0; o >>= 1) {
        s1 += __shfl_xor_sync(0xffffffffu, s1, o);
        s2 += __shfl_xor_sync(0xffffffffu, s2, o);
    }
    if (lane == 0) { g_s1[warp] = s1; g_s2[warp] = s2; }
}

// ---------------- K3: s2max (single block) ----------------
__global__ void k_max() {
    __shared__ float sm[1024];
    int t = threadIdx.x;
    float m = -1e30f;
    for (int i = t; i < NROW; i += 1024) m = fmaxf(m, g_s2[i]);
    sm[t] = m;
    __syncthreads();
    for (int o = 512; o > 0; o >>= 1) {
        if (t < o) sm[t] = fmaxf(sm[t], sm[t + o]);
        __syncthreads();
    }
    if (t == 0) g_s2max = sm[0];
}

// ---------------- K4a: zero ranks ----------------
__global__ void k_zero() {
    int i = blockIdx.x * blockDim.x + threadIdx.x;
    if (i < NROW) g_rank[i] = 0;
}

// ---------------- K4b: partial rank counts (counting sort ranks) ----------------
__global__ void k_rank_part() {
    __shared__ float tile[256];
    int j = blockIdx.x * 256 + threadIdx.x;
    float v = g_s2[j];
    int base = blockIdx.y * 1024;
    int rank = 0;
    for (int t0 = base; t0 < base + 1024; t0 += 256) {
        tile[threadIdx.x] = g_s2[t0 + threadIdx.x];
        __syncthreads();
#pragma unroll 8
        for (int u = 0; u < 256; u++) {
            float w = tile[u];
            rank += (int)((w < v) || (w == v && (t0 + u) < j));
        }
        __syncthreads();
    }
    atomicAdd(&g_rank[j], rank);
}

// ---------------- K4c: scatter into sorted order; compute p, q ----------------
__global__ void k_scatter() {
    int j = blockIdx.x * 256 + threadIdx.x;
    float v = g_s2[j];
    int r = g_rank[j];
    float s2m = g_s2max;
    float p = expf(v - s2m);
    float q = expf(SLOPE * (v - s2m));
    g_pj[j] = p; g_qj[j] = q;
    g_s2s[r] = v; g_perm[r] = j;
    g_ps[r] = p;  g_qs[r] = q;
}

// ---------------- K5: per-chunk fp64 sums of p*h, q*h (sorted order) ----------------
__global__ void k_chunk() {
    int cc = blockIdx.x;        // 128 chunks
    int c = threadIdx.x;        // 256 cols
    __shared__ int   sperm[CHUNK];
    __shared__ float sp[CHUNK], sq[CHUNK];
    if (threadIdx.x < CHUNK) {
        int m = cc * CHUNK + threadIdx.x;
        sperm[threadIdx.x] = g_perm[m];
        sp[threadIdx.x] = g_ps[m];
        sq[threadIdx.x] = g_qs[m];
    }
    __syncthreads();
    double ap = 0.0, aq = 0.0;
#pragma unroll 4
    for (int u = 0; u < CHUNK; u++) {
        float hv = g_h[(size_t)sperm[u] * DH + c];
        ap += (double)sp[u] * (double)hv;
        aq += (double)sq[u] * (double)hv;
    }
    g_chP[cc * DH + c] = ap;
    g_chQ[cc * DH + c] = aq;
    if (threadIdx.x == 0) {
        double a = 0.0, b = 0.0;
        for (int u = 0; u < CHUNK; u++) { a += (double)sp[u]; b += (double)sq[u]; }
        g_chSp[cc] = a; g_chSq[cc] = b;
    }
}

// ---------------- K6: scan chunk sums (in place -> exclusive offsets) ----------------
__global__ void k_scan() {
    int c = threadIdx.x;
    if (c < DH) {
        double r = 0.0;
        for (int cc = 0; cc < NCHUNK; cc++) { double t = g_chP[cc * DH + c]; g_chP[cc * DH + c] = r; r += t; }
        double r2 = 0.0;
        for (int cc = 0; cc < NCHUNK; cc++) { double t = g_chQ[cc * DH + c]; g_chQ[cc * DH + c] = r2; r2 += t; }
    } else if (c == DH) {
        double r = 0.0;
        for (int cc = 0; cc < NCHUNK; cc++) { double t = g_chSp[cc]; g_chSp[cc] = r; r += t; }
    } else if (c == DH + 1) {
        double r = 0.0;
        for (int cc = 0; cc < NCHUNK; cc++) { double t = g_chSq[cc]; g_chSq[cc] = r; r += t; }
    }
}

// ---------------- K7: full exclusive prefix arrays ----------------
__global__ void k_prefix() {
    int cc = blockIdx.x;
    int c = threadIdx.x;
    __shared__ int   sperm[CHUNK];
    __shared__ float sp[CHUNK], sq[CHUNK];
    if (threadIdx.x < CHUNK) {
        int m = cc * CHUNK + threadIdx.x;
        sperm[threadIdx.x] = g_perm[m];
        sp[threadIdx.x] = g_ps[m];
        sq[threadIdx.x] = g_qs[m];
    }
    __syncthreads();
    double rp = g_chP[cc * DH + c];
    double rq = g_chQ[cc * DH + c];
    for (int u = 0; u < CHUNK; u++) {
        int m = cc * CHUNK + u;
        g_PreP[(size_t)m * DH + c] = rp;
        g_PreQ[(size_t)m * DH + c] = rq;
        float hv = g_h[(size_t)sperm[u] * DH + c];
        rp += (double)sp[u] * (double)hv;
        rq += (double)sq[u] * (double)hv;
    }
    if (cc == NCHUNK - 1) {
        g_PreP[(size_t)NROW * DH + c] = rp;
        g_PreQ[(size_t)NROW * DH + c] = rq;
    }
    if (c == 0) {
        double a = g_chSp[cc], b = g_chSq[cc];
        for (int u = 0; u < CHUNK; u++) {
            int m = cc * CHUNK + u;
            g_SpPre[m] = a; g_SqPre[m] = b;
            a += (double)sp[u]; b += (double)sq[u];
        }
        if (cc == NCHUNK - 1) { g_SpPre[NROW] = a; g_SqPre[NROW] = b; }
    }
}

// ---------------- K8: out rows + per-row att coefficients ----------------
__global__ void k_out(const float* __restrict__ a_b, float* __restrict__ out) {
    int i = blockIdx.x;
    int c = threadIdx.x;
    __shared__ double sA, sB;
    __shared__ int sK;
    if (c == 0) {
        float cb = a_b[0];
        float s1 = g_s1[i];
        float s2m = g_s2max;
        float u = s1 + cb + s2m;
        float m = u > 0.f ? u : SLOPE * u;          // exact row max of f(x)
        float alpha = expf(u - m);
        float beta  = expf(SLOPE * u - m);
        float t = -(s1 + cb);                       // x>0  <=>  s2[j] > t
        int lo = 0, hi = NROW;
        while (lo < hi) {
            int mid = (lo + hi) >> 1;
            if (g_s2s[mid] > t) hi = mid; else lo = mid + 1;
        }
        int k = lo;
        double Z = (double)alpha * (g_SpPre[NROW] - g_SpPre[k]) + (double)beta * g_SqPre[k];
        sA = (double)alpha / Z;
        sB = (double)beta / Z;
        sK = k;
        g_rowA[i] = (float)((double)alpha / Z);
        g_rowB[i] = (float)((double)beta / Z);
        g_rowT[i] = t;
    }
    __syncthreads();
    int k = sK;
    double totP = g_PreP[(size_t)NROW * DH + c];
    double v = sA * (totP - g_PreP[(size_t)k * DH + c]) + sB * g_PreQ[(size_t)k * DH + c];
    float f = (float)v;
    out[(size_t)i * DH + c] = f > 0.f ? f : SLOPE * f;
}

// ---------------- K9: materialize att (268 MB; HBM-bound) ----------------
__global__ void k_att(float* __restrict__ att) {
    const int TJ = 1024, TR = 32;
    int j0 = blockIdx.x * TJ;
    int i0 = blockIdx.y * TR;
    int t = threadIdx.x;
    int j = j0 + t * 4;
    float4 p = *(const float4*)&g_pj[j];
    float4 q = *(const float4*)&g_qj[j];
    float4 s = *(const float4*)&g_s2[j];
#pragma unroll 4
    for (int r = 0; r < TR; r++) {
        int i = i0 + r;
        float A = __ldg(&g_rowA[i]);
        float B = __ldg(&g_rowB[i]);
        float T = __ldg(&g_rowT[i]);
        float4 o;
        o.x = s.x > T ? A * p.x : B * q.x;
        o.y = s.y > T ? A * p.y : B * q.y;
        o.z = s.z > T ? A * p.z : B * q.z;
        o.w = s.w > T ? A * p.w : B * q.w;
        *(float4*)&att[(size_t)i * NROW + j] = o;
    }
}

// ---------------- launch ----------------
extern "C" void kernel_launch(void* const* d_in, const int* in_sizes, int n_in,
                              void* d_out, int out_size) {
    const float* doc = (const float*)d_in[0];
    const float* W   = (const float*)d_in[1];
    const float* Wb  = (const float*)d_in[2];
    const float* a   = (const float*)d_in[3];
    const float* ab  = (const float*)d_in[4];
    float* out = (float*)d_out;                  // [8192 x 256]
    float* att = out + (size_t)NROW * DH;        // [8192 x 8192]

    k_gemm<<<dim3(64, 2), 256>>>(doc, W, Wb);
    k_s<<<1024, 256>>>(a);
    k_max<<<1, 1024>>>();
    k_zero<<<NROW / 256, 256>>>();
    k_rank_part<<<dim3(32, 8), 256>>>();
    k_scatter<<<32, 256>>>();
    k_chunk<<<NCHUNK, 256>>>();
    k_scan<<<1, 288>>>();
    k_prefix<<<NCHUNK, 256>>>();
    k_out<<<NROW, 256>>>(ab, out);
    k_att<<<dim3(NROW / 1024, NROW / 32), 256>>>(att);
}